// round 14
// baseline (speedup 1.0000x reference)
#include <cuda_runtime.h>
#include <cstddef>

// Problem constants
#define BATCH   16
#define IN_CH   2
#define FDIM    2048
#define TDIM    1024
#define NBANDS  64
#define BANDSZ  32      // FDIM / NBANDS
#define EMB     128

#define T_CHUNK 256
#define THREADS 256

// FINAL KERNEL (champion, reproduced 3x at ~120.5us kernel / 78% DRAM).
// HBM-bound at the empirically-measured wall (~6.2 TB/s achieved on a minimal
// 768 MB mixed read/write stream). Measured-falsified alternatives:
//  - interleaved channel loads / 32-reg cap: break front-batched MLP (67-68%)
//  - shfl-based reduction: +4 regs, lower occ (77.0%)
//  - two-kernel pure-direction split: no gain (76.1%)
//  - larger t-tiles, contiguous-per-warp writes: neutral-worse.
__global__ __launch_bounds__(THREADS)
void bandsplit_kernel(const float* __restrict__ x,
                      const float* __restrict__ W,
                      const float* __restrict__ bias,
                      float* __restrict__ out)
{
    // partial sums: [ch][fgroup][t4col] as float4 -> 2*4*64*16B = 8 KB
    __shared__ float4 part[IN_CH][4][T_CHUNK / 4];
    // final means: [ch][t] -> 2 KB
    __shared__ float xm[IN_CH][T_CHUNK];

    const int g  = blockIdx.x;
    const int tc = g & 3;               // t-chunk index (TDIM / T_CHUNK = 4)
    const int n  = (g >> 2) & 63;       // band
    const int b  = g >> 8;              // batch
    const int t0 = tc * T_CHUNK;
    const int tid = threadIdx.x;

    // ---------------- Phase 1: band sum, float4, 4-way f-split --------------
    // Two separate per-channel load loops: proven SASS schedule (front-batched
    // MLP). Do NOT interleave channels or cap registers — both measured slower.
    const int t4 = tid & 63;            // float4 column (64 cols = 256 t)
    const int fg = tid >> 6;            // f-group: 8 rows each

    const size_t ft   = (size_t)FDIM * TDIM;
    const int    row4 = TDIM / 4;       // 256 float4 per f-row

    const float4* xp0 = (const float4*)(x + (size_t)b * IN_CH * ft
                                          + (size_t)(n * BANDSZ + fg * 8) * TDIM
                                          + t0) + t4;
    const float4* xp1 = xp0 + ft / 4;

    float4 s0 = make_float4(0.f, 0.f, 0.f, 0.f);
    float4 s1 = make_float4(0.f, 0.f, 0.f, 0.f);
    #pragma unroll
    for (int f = 0; f < 8; f++) {
        const float4 v = __ldcs(xp0 + (size_t)f * row4);
        s0.x += v.x; s0.y += v.y; s0.z += v.z; s0.w += v.w;
    }
    #pragma unroll
    for (int f = 0; f < 8; f++) {
        const float4 v = __ldcs(xp1 + (size_t)f * row4);
        s1.x += v.x; s1.y += v.y; s1.z += v.z; s1.w += v.w;
    }
    part[0][fg][t4] = s0;
    part[1][fg][t4] = s1;
    __syncthreads();

    // Cross-f reduction: 128 threads combine the 4 partials per (c, t4).
    if (tid < 128) {
        const int c   = tid >> 6;
        const int tc4 = tid & 63;
        const float4 p0 = part[c][0][tc4];
        const float4 p1 = part[c][1][tc4];
        const float4 p2 = part[c][2][tc4];
        const float4 p3 = part[c][3][tc4];
        const float inv = 1.f / BANDSZ;
        xm[c][tc4 * 4 + 0] = (p0.x + p1.x + p2.x + p3.x) * inv;
        xm[c][tc4 * 4 + 1] = (p0.y + p1.y + p2.y + p3.y) * inv;
        xm[c][tc4 * 4 + 2] = (p0.z + p1.z + p2.z + p3.z) * inv;
        xm[c][tc4 * 4 + 3] = (p0.w + p1.w + p2.w + p3.w) * inv;
    }

    // Load weights while the reduction settles (independent of smem).
    const int e4   = (tid & 31) * 4;
    const int trow = tid >> 5;

    const float4 w0 = *(const float4*)(W + ((size_t)n * IN_CH + 0) * EMB + e4);
    const float4 w1 = *(const float4*)(W + ((size_t)n * IN_CH + 1) * EMB + e4);
    const float4 bb = *(const float4*)(bias + (size_t)n * EMB + e4);

    __syncthreads();

    // ---------------- Phase 2: project to EMB and write ---------------------
    // Interleaved ordering (warp strides 4 KB): measured best write schedule.
    // out index: ((b*NBANDS + n)*TDIM + t)*EMB + e
    float4* op = (float4*)(out + (((size_t)b * NBANDS + n) * TDIM + t0) * EMB + e4);

    #pragma unroll 8
    for (int i = 0; i < T_CHUNK / 8; i++) {
        const int t = trow + i * 8;
        const float m0 = xm[0][t];      // warp-uniform smem broadcast
        const float m1 = xm[1][t];
        float4 r;
        r.x = fmaf(m0, w0.x, fmaf(m1, w1.x, bb.x));
        r.y = fmaf(m0, w0.y, fmaf(m1, w1.y, bb.y));
        r.z = fmaf(m0, w0.z, fmaf(m1, w1.z, bb.z));
        r.w = fmaf(m0, w0.w, fmaf(m1, w1.w, bb.w));
        __stcs(op + (size_t)t * (EMB / 4), r);
    }
}

extern "C" void kernel_launch(void* const* d_in, const int* in_sizes, int n_in,
                              void* d_out, int out_size)
{
    const float* x    = (const float*)d_in[0];
    const float* W    = (const float*)d_in[1];
    const float* bias = (const float*)d_in[2];
    float* out        = (float*)d_out;

    const int grid = BATCH * NBANDS * (TDIM / T_CHUNK);  // 4096
    bandsplit_kernel<<<grid, THREADS>>>(x, W, bias, out);
}

// round 15
// speedup vs baseline: 1.0106x; 1.0106x over previous
#include <cuda_runtime.h>
#include <cstddef>

// Problem constants
#define BATCH   16
#define IN_CH   2
#define FDIM    2048
#define TDIM    1024
#define NBANDS  64
#define BANDSZ  32      // FDIM / NBANDS
#define EMB     128

#define T_CHUNK 256
#define THREADS 512

__global__ __launch_bounds__(THREADS)
void bandsplit_kernel(const float* __restrict__ x,
                      const float* __restrict__ W,
                      const float* __restrict__ bias,
                      float* __restrict__ out)
{
    // partial sums: [ch][fgroup][t4col] as float4 -> 2*4*64*16B = 8 KB
    __shared__ float4 part[IN_CH][4][T_CHUNK / 4];
    // final means: [ch][t] -> 2 KB
    __shared__ float xm[IN_CH][T_CHUNK];

    const int g  = blockIdx.x;
    const int tc = g & 3;               // t-chunk index (TDIM / T_CHUNK = 4)
    const int n  = (g >> 2) & 63;       // band
    const int b  = g >> 8;              // batch
    const int t0 = tc * T_CHUNK;
    const int tid = threadIdx.x;

    // ---------------- Phase 1: band sum, float4, ch+f split across threads --
    // 512 threads: tid -> (c, fg, t4). Each thread runs ONE 8-load channel
    // loop (the proven front-batched schedule) with a single float4 acc.
    const int t4 = tid & 63;            // float4 column (64 cols = 256 t)
    const int fg = (tid >> 6) & 3;      // f-group: 8 rows each
    const int c  = tid >> 8;            // channel 0/1

    const size_t ft   = (size_t)FDIM * TDIM;
    const int    row4 = TDIM / 4;       // 256 float4 per f-row

    const float4* xp = (const float4*)(x + ((size_t)(b * IN_CH + c)) * ft
                                         + (size_t)(n * BANDSZ + fg * 8) * TDIM
                                         + t0) + t4;

    float4 s = make_float4(0.f, 0.f, 0.f, 0.f);
    #pragma unroll
    for (int f = 0; f < 8; f++) {
        const float4 v = __ldcs(xp + (size_t)f * row4);
        s.x += v.x; s.y += v.y; s.z += v.z; s.w += v.w;
    }
    part[c][fg][t4] = s;
    __syncthreads();

    // Cross-f reduction: 128 threads combine the 4 partials per (c, t4).
    if (tid < 128) {
        const int cc  = tid >> 6;
        const int tc4 = tid & 63;
        const float4 p0 = part[cc][0][tc4];
        const float4 p1 = part[cc][1][tc4];
        const float4 p2 = part[cc][2][tc4];
        const float4 p3 = part[cc][3][tc4];
        const float inv = 1.f / BANDSZ;
        xm[cc][tc4 * 4 + 0] = (p0.x + p1.x + p2.x + p3.x) * inv;
        xm[cc][tc4 * 4 + 1] = (p0.y + p1.y + p2.y + p3.y) * inv;
        xm[cc][tc4 * 4 + 2] = (p0.z + p1.z + p2.z + p3.z) * inv;
        xm[cc][tc4 * 4 + 3] = (p0.w + p1.w + p2.w + p3.w) * inv;
    }

    // Load weights while the reduction settles (independent of smem).
    const int e4   = (tid & 31) * 4;
    const int trow = tid >> 5;          // 0..15

    const float4 w0 = *(const float4*)(W + ((size_t)n * IN_CH + 0) * EMB + e4);
    const float4 w1 = *(const float4*)(W + ((size_t)n * IN_CH + 1) * EMB + e4);
    const float4 bb = *(const float4*)(bias + (size_t)n * EMB + e4);

    __syncthreads();

    // ---------------- Phase 2: project to EMB and write ---------------------
    // Interleaved ordering: 16 warps stride 8 KB, jointly covering the chunk.
    // out index: ((b*NBANDS + n)*TDIM + t)*EMB + e
    float4* op = (float4*)(out + (((size_t)b * NBANDS + n) * TDIM + t0) * EMB + e4);

    #pragma unroll 8
    for (int i = 0; i < T_CHUNK / 16; i++) {
        const int t = trow + i * 16;
        const float m0 = xm[0][t];      // warp-uniform smem broadcast
        const float m1 = xm[1][t];
        float4 r;
        r.x = fmaf(m0, w0.x, fmaf(m1, w1.x, bb.x));
        r.y = fmaf(m0, w0.y, fmaf(m1, w1.y, bb.y));
        r.z = fmaf(m0, w0.z, fmaf(m1, w1.z, bb.z));
        r.w = fmaf(m0, w0.w, fmaf(m1, w1.w, bb.w));
        __stcs(op + (size_t)t * (EMB / 4), r);
    }
}

extern "C" void kernel_launch(void* const* d_in, const int* in_sizes, int n_in,
                              void* d_out, int out_size)
{
    const float* x    = (const float*)d_in[0];
    const float* W    = (const float*)d_in[1];
    const float* bias = (const float*)d_in[2];
    float* out        = (float*)d_out;

    const int grid = BATCH * NBANDS * (TDIM / T_CHUNK);  // 4096
    bandsplit_kernel<<<grid, THREADS>>>(x, W, bias, out);
}

// round 16
// speedup vs baseline: 1.0156x; 1.0049x over previous
#include <cuda_runtime.h>
#include <cstddef>

// Problem constants
#define BATCH   16
#define IN_CH   2
#define FDIM    2048
#define TDIM    1024
#define NBANDS  64
#define BANDSZ  32      // FDIM / NBANDS
#define EMB     128

#define T_CHUNK 256
#define THREADS 512

__global__ __launch_bounds__(THREADS, 4)
void bandsplit_kernel(const float* __restrict__ x,
                      const float* __restrict__ W,
                      const float* __restrict__ bias,
                      float* __restrict__ out)
{
    // partial sums: [ch][fgroup][t4col] as float4 -> 2*4*64*16B = 8 KB
    __shared__ float4 part[IN_CH][4][T_CHUNK / 4];
    // final means: [ch][t] -> 2 KB
    __shared__ float xm[IN_CH][T_CHUNK];

    const int g  = blockIdx.x;
    const int tc = g & 3;               // t-chunk index (TDIM / T_CHUNK = 4)
    const int n  = (g >> 2) & 63;       // band
    const int b  = g >> 8;              // batch
    const int t0 = tc * T_CHUNK;
    const int tid = threadIdx.x;

    // ---------------- Phase 1: band sum, float4, ch+f split across threads --
    // 512 threads: tid -> (c, fg, t4). Each thread runs ONE 8-load channel
    // loop (proven front-batched schedule) with a single float4 acc.
    const int t4 = tid & 63;            // float4 column (64 cols = 256 t)
    const int fg = (tid >> 6) & 3;      // f-group: 8 rows each
    const int c  = tid >> 8;            // channel 0/1

    const size_t ft   = (size_t)FDIM * TDIM;
    const int    row4 = TDIM / 4;       // 256 float4 per f-row

    const float4* xp = (const float4*)(x + ((size_t)(b * IN_CH + c)) * ft
                                         + (size_t)(n * BANDSZ + fg * 8) * TDIM
                                         + t0) + t4;

    float4 s = make_float4(0.f, 0.f, 0.f, 0.f);
    #pragma unroll
    for (int f = 0; f < 8; f++) {
        const float4 v = __ldcs(xp + (size_t)f * row4);
        s.x += v.x; s.y += v.y; s.z += v.z; s.w += v.w;
    }
    part[c][fg][t4] = s;
    __syncthreads();

    // Cross-f reduction: 128 threads combine the 4 partials per (c, t4).
    if (tid < 128) {
        const int cc  = tid >> 6;
        const int tc4 = tid & 63;
        const float4 p0 = part[cc][0][tc4];
        const float4 p1 = part[cc][1][tc4];
        const float4 p2 = part[cc][2][tc4];
        const float4 p3 = part[cc][3][tc4];
        const float inv = 1.f / BANDSZ;
        xm[cc][tc4 * 4 + 0] = (p0.x + p1.x + p2.x + p3.x) * inv;
        xm[cc][tc4 * 4 + 1] = (p0.y + p1.y + p2.y + p3.y) * inv;
        xm[cc][tc4 * 4 + 2] = (p0.z + p1.z + p2.z + p3.z) * inv;
        xm[cc][tc4 * 4 + 3] = (p0.w + p1.w + p2.w + p3.w) * inv;
    }

    // Load weights while the reduction settles (independent of smem).
    const int e4   = (tid & 31) * 4;
    const int trow = tid >> 5;          // 0..15

    const float4 w0 = *(const float4*)(W + ((size_t)n * IN_CH + 0) * EMB + e4);
    const float4 w1 = *(const float4*)(W + ((size_t)n * IN_CH + 1) * EMB + e4);
    const float4 bb = *(const float4*)(bias + (size_t)n * EMB + e4);

    __syncthreads();

    // ---------------- Phase 2: project to EMB and write ---------------------
    // Interleaved ordering: 16 warps stride 8 KB, jointly covering the chunk.
    // out index: ((b*NBANDS + n)*TDIM + t)*EMB + e
    float4* op = (float4*)(out + (((size_t)b * NBANDS + n) * TDIM + t0) * EMB + e4);

    #pragma unroll 8
    for (int i = 0; i < T_CHUNK / 16; i++) {
        const int t = trow + i * 16;
        const float m0 = xm[0][t];      // warp-uniform smem broadcast
        const float m1 = xm[1][t];
        float4 r;
        r.x = fmaf(m0, w0.x, fmaf(m1, w1.x, bb.x));
        r.y = fmaf(m0, w0.y, fmaf(m1, w1.y, bb.y));
        r.z = fmaf(m0, w0.z, fmaf(m1, w1.z, bb.z));
        r.w = fmaf(m0, w0.w, fmaf(m1, w1.w, bb.w));
        __stcs(op + (size_t)t * (EMB / 4), r);
    }
}

extern "C" void kernel_launch(void* const* d_in, const int* in_sizes, int n_in,
                              void* d_out, int out_size)
{
    const float* x    = (const float*)d_in[0];
    const float* W    = (const float*)d_in[1];
    const float* bias = (const float*)d_in[2];
    float* out        = (float*)d_out;

    const int grid = BATCH * NBANDS * (TDIM / T_CHUNK);  // 4096
    bandsplit_kernel<<<grid, THREADS>>>(x, W, bias, out);
}